// round 16
// baseline (speedup 1.0000x reference)
#include <cuda_runtime.h>
#include <stdint.h>

// GenerativeUpBlock: pruned generative transpose conv 3x3x3 stride 2.
//   d_in[0] in_feats  f32 [NP,64]   d_in[1] weights f32 [27,64,32]
//   d_in[2] bias      f32 [32]      d_in[3] in_coords [NP,4] (int32 or int64)
//   d_in[4] guide_coords [NG,4]     out: f32 [NG,32]

#define TABLE_SIZE (1 << 21)           // 128^3 dense stride-2 lattice
#define MAXG 400000
#define NOFF 27
#define GB2 20                         // chunks per (offset, k-half)
#define CWARPS 4                       // warps per compute block (128 threads)
#define RPI 4                          // matches per warp-iteration

// Table stores (input_row + 1); 0 = empty. Zero-initialized device globals make
// the initial state valid without an 8MB fill; k_clear (after compute) restores
// zeros for the next graph replay.
__device__ __align__(16) int g_table[TABLE_SIZE];
__device__ int               g_cnt[NOFF];
__device__ int               g_is64;
__device__ __align__(16) int2 g_pairs[(size_t)NOFF * MAXG + 4]; // +4: int4 overread pad

// ---- packed fp32x2 helpers (Blackwell FFMA2) -------------------------------
__device__ __forceinline__ unsigned long long pk2(float a, float b) {
    unsigned long long r;
    asm("mov.b64 %0, {%1, %2};" : "=l"(r) : "f"(a), "f"(b));
    return r;
}
__device__ __forceinline__ void upk2(unsigned long long v, float& a, float& b) {
    asm("mov.b64 {%0, %1}, %2;" : "=f"(a), "=f"(b) : "l"(v));
}
#define FFMA2(d, a, b, c) \
    asm("fma.rn.f32x2 %0, %1, %2, %3;" : "=l"(d) : "l"(a), "l"(b), "l"(c))

__device__ __forceinline__ void red_add_v4(float* p, float x, float y, float z, float w) {
    asm volatile("red.global.add.v4.f32 [%0], {%1, %2, %3, %4};"
                 :: "l"(p), "f"(x), "f"(y), "f"(z), "f"(w) : "memory");
}

// Read coord row r as (x,y,z), branching on detected dtype (vector loads).
__device__ __forceinline__ void read_coord(const int* __restrict__ base, int r, int is64,
                                           int& x, int& y, int& z) {
    const int4* p = (const int4*)base;
    if (is64) {
        int4 lo = __ldg(&p[2 * r]);
        int4 hi = __ldg(&p[2 * r + 1]);
        x = lo.z; y = hi.x; z = hi.z;
    } else {
        int4 v = __ldg(&p[r]);
        x = v.y; y = v.z; z = v.w;
    }
}

// ---------------------------------------------------------------------------
// Kernel 1: dtype probe + reset per-offset counters (1 block).
// ---------------------------------------------------------------------------
__global__ void k_init(const int* __restrict__ ic) {
    if (threadIdx.x < 32) {
        int nz = (ic[2 * threadIdx.x + 1] != 0);   // odd int32 slots zero iff int64
        unsigned any = __ballot_sync(0xffffffffu, nz);
        if (threadIdx.x == 0) g_is64 = (any == 0u);
    }
    if (threadIdx.x >= 32 && threadIdx.x < 32 + NOFF) g_cnt[threadIdx.x - 32] = 0;
}

// ---------------------------------------------------------------------------
// Kernel 2: scatter input rows into dense table (value = row + 1).
// ---------------------------------------------------------------------------
__global__ void k_scatter(const int* __restrict__ ic, int np) {
    int i = blockIdx.x * blockDim.x + threadIdx.x;
    if (i >= np) return;
    int x, y, z;
    read_coord(ic, i, g_is64, x, y, z);
    if ((unsigned)x > 255u || (unsigned)y > 255u || (unsigned)z > 255u) return;
    if ((x | y | z) & 1) return;
    int lin = (x >> 1) | ((y >> 1) << 7) | ((z >> 1) << 14);
    g_table[lin] = i + 1;
}

// ---------------------------------------------------------------------------
// Kernel 2b: clear the exact entries scatter wrote (restores all-zero state
// for the next graph replay). Runs AFTER k_compute (off the critical path).
// ---------------------------------------------------------------------------
__global__ void k_clear(const int* __restrict__ ic, int np) {
    int i = blockIdx.x * blockDim.x + threadIdx.x;
    if (i >= np) return;
    int x, y, z;
    read_coord(ic, i, g_is64, x, y, z);
    if ((unsigned)x > 255u || (unsigned)y > 255u || (unsigned)z > 255u) return;
    if ((x | y | z) & 1) return;
    int lin = (x >> 1) | ((y >> 1) << 7) | ((z >> 1) << 14);
    g_table[lin] = 0;
}

// ---------------------------------------------------------------------------
// Kernel 3: match (block-aggregated pair emission) + out-row init
// (bias where generated, zero elsewhere).
// ---------------------------------------------------------------------------
__global__ void k_match(const int* __restrict__ gc, const float* __restrict__ bias,
                        float* __restrict__ out, int ng) {
    __shared__ int scnt[NOFF];
    __shared__ int sbase[NOFF];
    __shared__ float4 sb[8];
    const int tid = threadIdx.x;
    if (tid < NOFF) scnt[tid] = 0;
    if (tid < 8) sb[tid] = __ldg(&((const float4*)bias)[tid]);
    __syncthreads();

    const int g = blockIdx.x * blockDim.x + tid;
    int nm = 0;
    int mo[8], mi[8], mslot[8];

    if (g < ng) {
        int qx, qy, qz;
        read_coord(gc, g, g_is64, qx, qy, qz);
        int ox = qx & 1, oy = qy & 1, oz = qz & 1;
        int ndx = ox ? 2 : 1, ndy = oy ? 2 : 1, ndz = oz ? 2 : 1;

        for (int a = 0; a < ndx; a++) {
            int dx = ox ? (a * 2 - 1) : 0;
            int px = qx - dx;
            if ((unsigned)px > 254u) continue;
            for (int b = 0; b < ndy; b++) {
                int dy = oy ? (b * 2 - 1) : 0;
                int py = qy - dy;
                if ((unsigned)py > 254u) continue;
                for (int c = 0; c < ndz; c++) {
                    int dz = oz ? (c * 2 - 1) : 0;
                    int pz = qz - dz;
                    if ((unsigned)pz > 254u) continue;
                    int lin = (px >> 1) | ((py >> 1) << 7) | ((pz >> 1) << 14);
                    int idx = g_table[lin];
                    if (idx > 0) {
                        mo[nm] = (dx + 1) * 9 + (dy + 1) * 3 + (dz + 1);
                        mi[nm] = idx - 1;
                        nm++;
                    }
                }
            }
        }
        float4* orow = (float4*)(out + (size_t)g * 32);
        if (nm) {
#pragma unroll
            for (int j = 0; j < 8; j++) orow[j] = sb[j];
        } else {
            float4 z4 = make_float4(0.f, 0.f, 0.f, 0.f);
#pragma unroll
            for (int j = 0; j < 8; j++) orow[j] = z4;
        }
    }

    for (int m = 0; m < nm; m++) mslot[m] = atomicAdd(&scnt[mo[m]], 1);
    __syncthreads();
    if (tid < NOFF && scnt[tid] > 0) sbase[tid] = atomicAdd(&g_cnt[tid], scnt[tid]);
    __syncthreads();
    for (int m = 0; m < nm; m++) {
        int o = mo[m];
        g_pairs[(size_t)o * MAXG + sbase[o] + mslot[m]] = make_int2(g, mi[m]);
    }
}

// ---------------------------------------------------------------------------
// Kernel 4: per-(offset, k-half) gather-GEMV, 4 matches per warp-iteration.
// K-SPLIT: each block holds only 32 k-rows of W[o] (16 packed f32x2 regs),
// halving register pressure -> 6 blocks/SM (24 warps) instead of 4 (16).
// Both k-halves red.add into the same output row.
// Each lane gathers one half-row quarter: lane>>3 selects the match,
// lane&7 the float4 within the 32-float half-row (1 LDG.128/lane/iter,
// 4 rows in flight). Staged rows read back as ulonglong2 (LDS.128 broadcast)
// feeding fma.rn.f32x2. Accumulators transposed via shuffles, reduced with
// red.global.add.v4.f32 from 8 lanes. Double-buffered, depth-1 pipeline.
// ---------------------------------------------------------------------------
__global__ void __launch_bounds__(128, 6) k_compute(const float* __restrict__ feats,
                                                    const float* __restrict__ W,
                                                    float* __restrict__ out) {
    const int o     = blockIdx.x % NOFF;
    const int h     = (blockIdx.x / NOFF) & 1;        // k-half
    const int chunk = blockIdx.x / (NOFF * 2);
    const int lane  = threadIdx.x & 31;
    const int warp  = threadIdx.x >> 5;
    const int rsel  = lane >> 3;                      // which match this lane loads
    const int c8    = lane & 7;                       // float4 index in half-row

    __shared__ __align__(16) float4 sf[CWARPS][2][RPI][8]; // [warp][buf][row][8xf4]

    // Packed weights for this k-half: w2[k] = {W[o][h*32+2k][lane], W[o][h*32+2k+1][lane]}
    unsigned long long w2[16];
    const float* wp = W + o * (64 * 32) + h * (32 * 32);
#pragma unroll
    for (int k = 0; k < 16; k++)
        w2[k] = pk2(__ldg(&wp[(2 * k) * 32 + lane]), __ldg(&wp[(2 * k + 1) * 32 + lane]));

    const int n    = g_cnt[o];
    const int NW   = GB2 * CWARPS;
    const int wid  = chunk * CWARPS + warp;
    const int step = RPI * NW;
    const int2* seg = &g_pairs[(size_t)o * MAXG];

    int p = RPI * wid;
    int4 q01, q23;
    if (p < n) {
        q01 = __ldg((const int4*)(seg + p));
        q23 = __ldg((const int4*)(seg + p) + 1);
    }
    float4 v;
    {
        int ry = (rsel == 0) ? q01.y : (rsel == 1) ? q01.w : (rsel == 2) ? q23.y : q23.w;
        if (p + rsel < n)
            v = __ldg(&((const float4*)(feats + (size_t)ry * 64 + h * 32))[c8]);
    }

    int buf = 0;
    while (p < n) {
        sf[warp][buf][rsel][c8] = v;
        __syncwarp();

        int gx[RPI];
        gx[0] = q01.x; gx[1] = q01.z; gx[2] = q23.x; gx[3] = q23.z;
        const int rem = n - p;                 // >=1

        // ---- prefetch next iteration ----
        int pn = p + step;
        int4 n01, n23;
        if (pn < n) {
            n01 = __ldg((const int4*)(seg + pn));
            n23 = __ldg((const int4*)(seg + pn) + 1);
            int ry = (rsel == 0) ? n01.y : (rsel == 1) ? n01.w : (rsel == 2) ? n23.y : n23.w;
            if (pn + rsel < n)
                v = __ldg(&((const float4*)(feats + (size_t)ry * 64 + h * 32))[c8]);
        }

        // ---- compute + reduce rows 0..3 (this k-half) ----
#pragma unroll
        for (int r = 0; r < RPI; r++) {
            if (r < rem) {
                const ulonglong2* srow = (const ulonglong2*)&sf[warp][buf][r][0];
                unsigned long long aA = 0ull, aB = 0ull;
#pragma unroll
                for (int k = 0; k < 8; k++) {
                    ulonglong2 t = srow[k];            // LDS.128 broadcast
                    FFMA2(aA, t.x, w2[2 * k],     aA);
                    FFMA2(aB, t.y, w2[2 * k + 1], aB);
                }
                float a0, a1, a2, a3;
                upk2(aA, a0, a1); upk2(aB, a2, a3);
                float acc = (a0 + a1) + (a2 + a3);
                int s = (lane * 4) & 31;
                float t0 = __shfl_sync(0xffffffffu, acc, s);
                float t1 = __shfl_sync(0xffffffffu, acc, s + 1);
                float t2 = __shfl_sync(0xffffffffu, acc, s + 2);
                float t3 = __shfl_sync(0xffffffffu, acc, s + 3);
                if (lane < 8)
                    red_add_v4(&out[(size_t)gx[r] * 32 + 4 * lane], t0, t1, t2, t3);
            }
        }

        p = pn; q01 = n01; q23 = n23; buf ^= 1;
    }
}

// ---------------------------------------------------------------------------
extern "C" void kernel_launch(void* const* d_in, const int* in_sizes, int n_in,
                              void* d_out, int out_size) {
    const float* feats = (const float*)d_in[0];
    const float* W     = (const float*)d_in[1];
    const float* bias  = (const float*)d_in[2];
    const int*   ic    = (const int*)d_in[3];
    const int*   gc    = (const int*)d_in[4];
    float*       out   = (float*)d_out;

    int np = in_sizes[0] / 64;
    int ng = in_sizes[4] / 4;
    if (ng > MAXG) ng = MAXG;

    k_init<<<1, 64>>>(ic);
    k_scatter<<<(np + 255) / 256, 256>>>(ic, np);
    k_match<<<(ng + 255) / 256, 256>>>(gc, bias, out, ng);
    k_compute<<<NOFF * 2 * GB2, 128>>>(feats, W, out);
    k_clear<<<(np + 255) / 256, 256>>>(ic, np);   // restore zero table for replay
}

// round 17
// speedup vs baseline: 1.3334x; 1.3334x over previous
#include <cuda_runtime.h>
#include <stdint.h>

// GenerativeUpBlock: pruned generative transpose conv 3x3x3 stride 2.
//   d_in[0] in_feats  f32 [NP,64]   d_in[1] weights f32 [27,64,32]
//   d_in[2] bias      f32 [32]      d_in[3] in_coords [NP,4] (int32 or int64)
//   d_in[4] guide_coords [NG,4]     out: f32 [NG,32]

#define TABLE_SIZE (1 << 21)           // 128^3 dense stride-2 lattice
#define MAXG 400000
#define NOFF 27
#define GB 40                          // chunks per offset in compute kernel
#define CWARPS 4                       // warps per compute block (128 threads)
#define RPI 4                          // matches per warp-iteration

// Table stores (input_row + 1); 0 = empty. Zero-initialized device globals make
// the initial state valid without an 8MB fill; k_clear (after compute) restores
// zeros for the next graph replay.
__device__ __align__(16) int g_table[TABLE_SIZE];
__device__ int               g_cnt[NOFF];
__device__ int               g_is64;
__device__ __align__(16) int2 g_pairs[(size_t)NOFF * MAXG + 4]; // +4: int4 overread pad

// ---- packed fp32x2 helpers (Blackwell FFMA2) -------------------------------
__device__ __forceinline__ unsigned long long pk2(float a, float b) {
    unsigned long long r;
    asm("mov.b64 %0, {%1, %2};" : "=l"(r) : "f"(a), "f"(b));
    return r;
}
__device__ __forceinline__ void upk2(unsigned long long v, float& a, float& b) {
    asm("mov.b64 {%0, %1}, %2;" : "=f"(a), "=f"(b) : "l"(v));
}
#define FFMA2(d, a, b, c) \
    asm("fma.rn.f32x2 %0, %1, %2, %3;" : "=l"(d) : "l"(a), "l"(b), "l"(c))

__device__ __forceinline__ void red_add_v4(float* p, float x, float y, float z, float w) {
    asm volatile("red.global.add.v4.f32 [%0], {%1, %2, %3, %4};"
                 :: "l"(p), "f"(x), "f"(y), "f"(z), "f"(w) : "memory");
}

// Read coord row r as (x,y,z), branching on detected dtype (vector loads).
__device__ __forceinline__ void read_coord(const int* __restrict__ base, int r, int is64,
                                           int& x, int& y, int& z) {
    const int4* p = (const int4*)base;
    if (is64) {
        int4 lo = __ldg(&p[2 * r]);
        int4 hi = __ldg(&p[2 * r + 1]);
        x = lo.z; y = hi.x; z = hi.z;
    } else {
        int4 v = __ldg(&p[r]);
        x = v.y; y = v.z; z = v.w;
    }
}

// ---------------------------------------------------------------------------
// Kernel 1: dtype probe + reset per-offset counters (1 block).
// ---------------------------------------------------------------------------
__global__ void k_init(const int* __restrict__ ic) {
    if (threadIdx.x < 32) {
        int nz = (ic[2 * threadIdx.x + 1] != 0);   // odd int32 slots zero iff int64
        unsigned any = __ballot_sync(0xffffffffu, nz);
        if (threadIdx.x == 0) g_is64 = (any == 0u);
    }
    if (threadIdx.x >= 32 && threadIdx.x < 32 + NOFF) g_cnt[threadIdx.x - 32] = 0;
}

// ---------------------------------------------------------------------------
// Kernel 2: scatter input rows into dense table (value = row + 1).
// ---------------------------------------------------------------------------
__global__ void k_scatter(const int* __restrict__ ic, int np) {
    int i = blockIdx.x * blockDim.x + threadIdx.x;
    if (i >= np) return;
    int x, y, z;
    read_coord(ic, i, g_is64, x, y, z);
    if ((unsigned)x > 255u || (unsigned)y > 255u || (unsigned)z > 255u) return;
    if ((x | y | z) & 1) return;
    int lin = (x >> 1) | ((y >> 1) << 7) | ((z >> 1) << 14);
    g_table[lin] = i + 1;
}

// ---------------------------------------------------------------------------
// Kernel 2b: clear the exact entries scatter wrote (restores all-zero state
// for the next graph replay). Runs AFTER k_compute (off the critical path).
// ---------------------------------------------------------------------------
__global__ void k_clear(const int* __restrict__ ic, int np) {
    int i = blockIdx.x * blockDim.x + threadIdx.x;
    if (i >= np) return;
    int x, y, z;
    read_coord(ic, i, g_is64, x, y, z);
    if ((unsigned)x > 255u || (unsigned)y > 255u || (unsigned)z > 255u) return;
    if ((x | y | z) & 1) return;
    int lin = (x >> 1) | ((y >> 1) << 7) | ((z >> 1) << 14);
    g_table[lin] = 0;
}

// ---------------------------------------------------------------------------
// Kernel 3: match (block-aggregated pair emission) + out-row init
// (bias where generated, zero elsewhere).
// ---------------------------------------------------------------------------
__global__ void k_match(const int* __restrict__ gc, const float* __restrict__ bias,
                        float* __restrict__ out, int ng) {
    __shared__ int scnt[NOFF];
    __shared__ int sbase[NOFF];
    __shared__ float4 sb[8];
    const int tid = threadIdx.x;
    if (tid < NOFF) scnt[tid] = 0;
    if (tid < 8) sb[tid] = __ldg(&((const float4*)bias)[tid]);
    __syncthreads();

    const int g = blockIdx.x * blockDim.x + tid;
    int nm = 0;
    int mo[8], mi[8], mslot[8];

    if (g < ng) {
        int qx, qy, qz;
        read_coord(gc, g, g_is64, qx, qy, qz);
        int ox = qx & 1, oy = qy & 1, oz = qz & 1;
        int ndx = ox ? 2 : 1, ndy = oy ? 2 : 1, ndz = oz ? 2 : 1;

        for (int a = 0; a < ndx; a++) {
            int dx = ox ? (a * 2 - 1) : 0;
            int px = qx - dx;
            if ((unsigned)px > 254u) continue;
            for (int b = 0; b < ndy; b++) {
                int dy = oy ? (b * 2 - 1) : 0;
                int py = qy - dy;
                if ((unsigned)py > 254u) continue;
                for (int c = 0; c < ndz; c++) {
                    int dz = oz ? (c * 2 - 1) : 0;
                    int pz = qz - dz;
                    if ((unsigned)pz > 254u) continue;
                    int lin = (px >> 1) | ((py >> 1) << 7) | ((pz >> 1) << 14);
                    int idx = g_table[lin];
                    if (idx > 0) {
                        mo[nm] = (dx + 1) * 9 + (dy + 1) * 3 + (dz + 1);
                        mi[nm] = idx - 1;
                        nm++;
                    }
                }
            }
        }
        float4* orow = (float4*)(out + (size_t)g * 32);
        if (nm) {
#pragma unroll
            for (int j = 0; j < 8; j++) orow[j] = sb[j];
        } else {
            float4 z4 = make_float4(0.f, 0.f, 0.f, 0.f);
#pragma unroll
            for (int j = 0; j < 8; j++) orow[j] = z4;
        }
    }

    for (int m = 0; m < nm; m++) mslot[m] = atomicAdd(&scnt[mo[m]], 1);
    __syncthreads();
    if (tid < NOFF && scnt[tid] > 0) sbase[tid] = atomicAdd(&g_cnt[tid], scnt[tid]);
    __syncthreads();
    for (int m = 0; m < nm; m++) {
        int o = mo[m];
        g_pairs[(size_t)o * MAXG + sbase[o] + mslot[m]] = make_int2(g, mi[m]);
    }
}

// ---------------------------------------------------------------------------
// Kernel 4: per-offset gather-GEMV, 4 matches per warp-iteration, DEPTH-2
// pipeline: pair records (sequential, dependency-free) are fetched TWO
// iterations ahead; feature rows are fetched ONE iteration ahead using pair
// records that resolved a full iteration earlier. This removes the serial
// pair->feature load chain from the per-iteration critical path.
// Lane halves each gather 2 feature rows (2 LDG.128/lane). Staged rows read
// back as ulonglong2 (LDS.128 broadcast) feeding fma.rn.f32x2; 4 accumulator
// chains per match. Weights packed f32x2 in registers. Accumulators
// transposed via shuffles, reduced with red.global.add.v4.f32 from 8 lanes.
// ---------------------------------------------------------------------------
__global__ void __launch_bounds__(128, 4) k_compute(const float* __restrict__ feats,
                                                    const float* __restrict__ W,
                                                    float* __restrict__ out) {
    const int o     = blockIdx.x % NOFF;
    const int chunk = blockIdx.x / NOFF;
    const int lane  = threadIdx.x & 31;
    const int warp  = threadIdx.x >> 5;
    const int half  = lane >> 4;          // row pair selector
    const int l16   = lane & 15;

    __shared__ __align__(16) float4 sf[CWARPS][2][RPI][16]; // [warp][buf][row][f4]

    // Packed weights: w2[k] = {W[o][2k][lane], W[o][2k+1][lane]}
    unsigned long long w2[32];
    const float* wp = W + o * (64 * 32);
#pragma unroll
    for (int k = 0; k < 32; k++)
        w2[k] = pk2(__ldg(&wp[(2 * k) * 32 + lane]), __ldg(&wp[(2 * k + 1) * 32 + lane]));

    const int n    = g_cnt[o];
    const int NW   = GB * CWARPS;
    const int wid  = chunk * CWARPS + warp;
    const int step = RPI * NW;
    const int2* seg = &g_pairs[(size_t)o * MAXG];

    int p = RPI * wid;
    // pairs for iteration 0 (qA) and iteration 1 (qB)
    int4 qA01, qA23, qB01, qB23;
    if (p < n) {
        qA01 = __ldg((const int4*)(seg + p));
        qA23 = __ldg((const int4*)(seg + p) + 1);
    }
    if (p + step < n) {
        qB01 = __ldg((const int4*)(seg + p + step));
        qB23 = __ldg((const int4*)(seg + p + step) + 1);
    }
    // features for iteration 0 from qA
    float4 v0, v1;
    {
        int r0y = half ? qA01.w : qA01.y;
        int r1y = half ? qA23.w : qA23.y;
        if (p + half < n)
            v0 = __ldg(&((const float4*)(feats + (size_t)r0y * 64))[l16]);
        if (p + 2 + half < n)
            v1 = __ldg(&((const float4*)(feats + (size_t)r1y * 64))[l16]);
    }

    int buf = 0;
    while (p < n) {
        sf[warp][buf][half][l16]     = v0;
        sf[warp][buf][2 + half][l16] = v1;
        __syncwarp();

        int gx[RPI];
        gx[0] = qA01.x; gx[1] = qA01.z; gx[2] = qA23.x; gx[3] = qA23.z;
        const int rem = n - p;                 // >=1

        // ---- prefetch: pairs two iterations ahead ----
        int pnn = p + 2 * step;
        int4 t01, t23;
        if (pnn < n) {
            t01 = __ldg((const int4*)(seg + pnn));
            t23 = __ldg((const int4*)(seg + pnn) + 1);
        }
        // ---- prefetch: features one iteration ahead (pairs already resolved) ----
        int pn = p + step;
        if (pn < n) {
            int r0y = half ? qB01.w : qB01.y;
            int r1y = half ? qB23.w : qB23.y;
            if (pn + half < n)
                v0 = __ldg(&((const float4*)(feats + (size_t)r0y * 64))[l16]);
            if (pn + 2 + half < n)
                v1 = __ldg(&((const float4*)(feats + (size_t)r1y * 64))[l16]);
        }

        // ---- compute + reduce rows 0..3 ----
#pragma unroll
        for (int r = 0; r < RPI; r++) {
            if (r < rem) {
                const ulonglong2* srow = (const ulonglong2*)&sf[warp][buf][r][0];
                unsigned long long aA = 0ull, aB = 0ull, aC = 0ull, aD = 0ull;
#pragma unroll
                for (int k = 0; k < 8; k++) {
                    ulonglong2 t0 = srow[2 * k];          // LDS.128 broadcast
                    ulonglong2 t1 = srow[2 * k + 1];
                    FFMA2(aA, t0.x, w2[4 * k + 0], aA);
                    FFMA2(aB, t0.y, w2[4 * k + 1], aB);
                    FFMA2(aC, t1.x, w2[4 * k + 2], aC);
                    FFMA2(aD, t1.y, w2[4 * k + 3], aD);
                }
                float a0, a1, a2, a3, a4, a5, a6, a7;
                upk2(aA, a0, a1); upk2(aB, a2, a3);
                upk2(aC, a4, a5); upk2(aD, a6, a7);
                float acc = ((a0 + a1) + (a2 + a3)) + ((a4 + a5) + (a6 + a7));
                int s = (lane * 4) & 31;
                float t0 = __shfl_sync(0xffffffffu, acc, s);
                float t1 = __shfl_sync(0xffffffffu, acc, s + 1);
                float t2 = __shfl_sync(0xffffffffu, acc, s + 2);
                float t3 = __shfl_sync(0xffffffffu, acc, s + 3);
                if (lane < 8)
                    red_add_v4(&out[(size_t)gx[r] * 32 + 4 * lane], t0, t1, t2, t3);
            }
        }

        p = pn;
        qA01 = qB01; qA23 = qB23;
        qB01 = t01;  qB23 = t23;
        buf ^= 1;
    }
}

// ---------------------------------------------------------------------------
extern "C" void kernel_launch(void* const* d_in, const int* in_sizes, int n_in,
                              void* d_out, int out_size) {
    const float* feats = (const float*)d_in[0];
    const float* W     = (const float*)d_in[1];
    const float* bias  = (const float*)d_in[2];
    const int*   ic    = (const int*)d_in[3];
    const int*   gc    = (const int*)d_in[4];
    float*       out   = (float*)d_out;

    int np = in_sizes[0] / 64;
    int ng = in_sizes[4] / 4;
    if (ng > MAXG) ng = MAXG;

    k_init<<<1, 64>>>(ic);
    k_scatter<<<(np + 255) / 256, 256>>>(ic, np);
    k_match<<<(ng + 255) / 256, 256>>>(gc, bias, out, ng);
    k_compute<<<NOFF * GB, 128>>>(feats, W, out);
    k_clear<<<(np + 255) / 256, 256>>>(ic, np);   // restore zero table for replay
}